// round 8
// baseline (speedup 1.0000x reference)
#include <cuda_runtime.h>
#include <cuda_bf16.h>
#include <math.h>

// Entry layout (52 bits used): [s:13][d:13][key:26]
//   key = ((i+1)<<3)|clamped  -> max(key) == last-write-wins (JAX scatter order)
#define KEY_MASK 0x3FFFFFFull
#define D_SHIFT 26
#define S_SHIFT 39

#define CSH 7                          // 128 rows per coarse bucket
#define NC_MAX 48
#define CAP_C 196608
#define NFPC 64                        // fine buckets per coarse (128 rows / 2)
#define NBF_MAX (NC_MAX * NFPC)        // 3072
#define CAP_F 4096

#define CB_TPB 256
#define CB_VPT 8
#define CB_PER (CB_TPB * CB_VPT)       // 2048 pairs / coarse-bin CTA
#define FB_TPB 256
#define FB_VPT 8
#define FB_PER (FB_TPB * FB_VPT)       // 2048 entries / fine-bin CTA
#define BPB_F (CAP_C / FB_PER)         // 96 fine-bin CTAs per coarse bucket
#define TILE_TPB 512
#define TILE_VPT 8                     // CAP_F / TILE_TPB

__device__ __align__(16) unsigned long long g_cbins[(size_t)NC_MAX * CAP_C];
__device__ __align__(16) unsigned long long g_fbins[(size_t)NBF_MAX * CAP_F];
__device__ int g_ccur[NC_MAX];
__device__ int g_fcur[NBF_MAX];

__global__ void reset_kernel(int nc, int nbf) {
    int i = blockIdx.x * blockDim.x + threadIdx.x;
    if (i < nc) g_ccur[i] = 0;
    if (i < nbf) g_fcur[i] = 0;
}

// ---------- Pass 1: pairs -> coarse buckets (segment-coalesced) ----------
__global__ void coarse_bin_kernel(const int* __restrict__ src,
                                  const int* __restrict__ dst,
                                  const int* __restrict__ len,
                                  int P, int maxpd, int nc) {
    __shared__ int s_cnt[NC_MAX];
    __shared__ int s_start[NC_MAX];
    __shared__ int s_goff[NC_MAX];
    extern __shared__ unsigned long long s_buf[];   // CB_PER * 8 = 16KB

    int tid = threadIdx.x;
    int base = blockIdx.x * CB_PER;
    if (tid < nc) s_cnt[tid] = 0;
    __syncthreads();

    unsigned long long e[CB_VPT];
    int bk[CB_VPT];
    int i0 = base + tid * CB_VPT;
    if (i0 + CB_VPT <= P) {
        int4 sa = *reinterpret_cast<const int4*>(src + i0);
        int4 sb = *reinterpret_cast<const int4*>(src + i0 + 4);
        int4 da = *reinterpret_cast<const int4*>(dst + i0);
        int4 db = *reinterpret_cast<const int4*>(dst + i0 + 4);
        int4 la = *reinterpret_cast<const int4*>(len + i0);
        int4 lb = *reinterpret_cast<const int4*>(len + i0 + 4);
        int sv[8] = {sa.x, sa.y, sa.z, sa.w, sb.x, sb.y, sb.z, sb.w};
        int dv[8] = {da.x, da.y, da.z, da.w, db.x, db.y, db.z, db.w};
        int lv[8] = {la.x, la.y, la.z, la.w, lb.x, lb.y, lb.z, lb.w};
#pragma unroll
        for (int j = 0; j < CB_VPT; j++) {
            unsigned key = ((unsigned)(i0 + j + 1) << 3)
                         | (unsigned)(min(lv[j], maxpd) - 1);
            e[j] = ((unsigned long long)sv[j] << S_SHIFT)
                 | ((unsigned long long)dv[j] << D_SHIFT)
                 | (unsigned long long)key;
            bk[j] = sv[j] >> CSH;
            atomicAdd(&s_cnt[bk[j]], 1);
        }
    } else {
#pragma unroll
        for (int j = 0; j < CB_VPT; j++) {
            int i = i0 + j;
            bk[j] = -1;
            if (i < P) {
                int s = src[i], d = dst[i], l = len[i];
                unsigned key = ((unsigned)(i + 1) << 3)
                             | (unsigned)(min(l, maxpd) - 1);
                e[j] = ((unsigned long long)s << S_SHIFT)
                     | ((unsigned long long)d << D_SHIFT)
                     | (unsigned long long)key;
                bk[j] = s >> CSH;
                atomicAdd(&s_cnt[bk[j]], 1);
            }
        }
    }
    __syncthreads();
    if (tid == 0) {
        int acc = 0;
        for (int b = 0; b < nc; b++) { s_start[b] = acc; acc += s_cnt[b]; }
    }
    __syncthreads();
    if (tid < nc) {
        int c = s_cnt[tid];
        int gb = (c > 0) ? atomicAdd(&g_ccur[tid], c) : 0;
        s_goff[tid] = gb - s_start[tid];
    }
    __syncthreads();
#pragma unroll
    for (int j = 0; j < CB_VPT; j++) {
        if (bk[j] >= 0) {
            int p = atomicAdd(&s_start[bk[j]], 1);
            s_buf[p] = e[j];
        }
    }
    __syncthreads();
    int tot = min(CB_PER, P - base);
    for (int k = tid; k < tot; k += CB_TPB) {
        unsigned long long ee = s_buf[k];
        int b = (int)(ee >> (S_SHIFT + CSH));
        int gpos = s_goff[b] + k;
        if ((unsigned)gpos < (unsigned)CAP_C)
            g_cbins[(size_t)b * CAP_C + gpos] = ee;
    }
}

// ---------- Pass 2: coarse bucket -> 64 fine buckets (2 rows each) ----------
__global__ void fine_bin_kernel() {
    __shared__ int s_cnt[NFPC];
    __shared__ int s_start[NFPC];
    __shared__ int s_goff[NFPC];
    extern __shared__ unsigned long long s_buf[];   // FB_PER * 8 = 16KB

    int c = blockIdx.x / BPB_F;
    int blk = blockIdx.x % BPB_F;
    int count = min(g_ccur[c], (int)CAP_C);
    int base = blk * FB_PER;
    if (base >= count) return;
    int tot = min(FB_PER, count - base);
    const unsigned long long* cb = g_cbins + (size_t)c * CAP_C + base;

    int tid = threadIdx.x;
    if (tid < NFPC) s_cnt[tid] = 0;
    __syncthreads();

    unsigned long long e[FB_VPT];
    int bk[FB_VPT];
#pragma unroll
    for (int j = 0; j < FB_VPT; j += 2) {
        int k2 = (j >> 1) * (FB_TPB * 2) + tid * 2;
        bk[j] = -1;
        bk[j + 1] = -1;
        if (k2 + 1 < tot) {
            ulonglong2 v = *reinterpret_cast<const ulonglong2*>(cb + k2);
            e[j] = v.x; e[j + 1] = v.y;
            bk[j]     = (int)(v.x >> (S_SHIFT + 1)) & (NFPC - 1);
            bk[j + 1] = (int)(v.y >> (S_SHIFT + 1)) & (NFPC - 1);
            atomicAdd(&s_cnt[bk[j]], 1);
            atomicAdd(&s_cnt[bk[j + 1]], 1);
        } else {
            for (int k = k2; k < tot && k < k2 + 2; k++) {
                int jj = j + (k - k2);
                e[jj] = cb[k];
                bk[jj] = (int)(e[jj] >> (S_SHIFT + 1)) & (NFPC - 1);
                atomicAdd(&s_cnt[bk[jj]], 1);
            }
        }
    }
    __syncthreads();
    if (tid == 0) {
        int acc = 0;
        for (int b = 0; b < NFPC; b++) { s_start[b] = acc; acc += s_cnt[b]; }
    }
    __syncthreads();
    if (tid < NFPC) {
        int cnt = s_cnt[tid];
        int gb = (cnt > 0) ? atomicAdd(&g_fcur[c * NFPC + tid], cnt) : 0;
        s_goff[tid] = gb - s_start[tid];
    }
    __syncthreads();
#pragma unroll
    for (int j = 0; j < FB_VPT; j++) {
        if (bk[j] >= 0) {
            int p = atomicAdd(&s_start[bk[j]], 1);
            s_buf[p] = e[j];
        }
    }
    __syncthreads();
    for (int k = tid; k < tot; k += FB_TPB) {
        unsigned long long ee = s_buf[k];
        int s = (int)(ee >> S_SHIFT);
        int gpos = s_goff[(s >> 1) & (NFPC - 1)] + k;
        if ((unsigned)gpos < (unsigned)CAP_F)
            g_fbins[(size_t)(s >> 1) * CAP_F + gpos] = ee;
    }
}

// ---------- Pass 3: fine bucket -> 2-row smem tile -> single output write ----
__global__ void tile_kernel(float* __restrict__ out, const float* __restrict__ bvals,
                            int n, int maxpd) {
    extern __shared__ int s_tile[];    // 2 * n ints = 48000B for n=6000
    __shared__ float s_bias[8];
    int tid = threadIdx.x;
    int bucket = blockIdx.x;
    int row0 = bucket * 2;
    int rows = min(2, n - row0);
    int tilesz = rows * n;

    if (tid < 8) s_bias[tid] = (tid < maxpd) ? bvals[tid] : 0.0f;
    {
        int4 z4 = make_int4(0, 0, 0, 0);
        int t4 = tilesz >> 2;
        for (int i = tid; i < t4; i += TILE_TPB)
            reinterpret_cast<int4*>(s_tile)[i] = z4;
        for (int i = (t4 << 2) + tid; i < tilesz; i += TILE_TPB) s_tile[i] = 0;
    }
    __syncthreads();

    int cnt = min(g_fcur[bucket], (int)CAP_F);
    const unsigned long long* bin = g_fbins + (size_t)bucket * CAP_F;

    // load entries once into registers; reuse in both phases
    int slot[TILE_VPT];
    int key[TILE_VPT];
    int myc = 0;
    for (int k = tid; k < cnt; k += TILE_TPB) {
        unsigned long long v = bin[k];
        int s = (int)(v >> S_SHIFT);
        int d = (int)(v >> D_SHIFT) & 0x1FFF;
        slot[myc] = (s - row0) * n + d;
        key[myc] = (int)(v & KEY_MASK);
        myc++;
    }
    // phase 1: plain racing writes (some writer wins)
#pragma unroll
    for (int j = 0; j < TILE_VPT; j++)
        if (j < myc) s_tile[slot[j]] = key[j];
    __syncthreads();
    // phase 2: repair — only true collisions pay an atomic
#pragma unroll
    for (int j = 0; j < TILE_VPT; j++)
        if (j < myc && s_tile[slot[j]] < key[j]) atomicMax(&s_tile[slot[j]], key[j]);
    __syncthreads();

    float* orow = out + (size_t)row0 * n;
    int tot4 = tilesz >> 2;
    for (int q = tid; q < tot4; q += TILE_TPB) {
        int4 k4 = reinterpret_cast<const int4*>(s_tile)[q];
        float4 f;
        f.x = k4.x ? s_bias[k4.x & 7] : 0.0f;
        f.y = k4.y ? s_bias[k4.y & 7] : 0.0f;
        f.z = k4.z ? s_bias[k4.z & 7] : 0.0f;
        f.w = k4.w ? s_bias[k4.w & 7] : 0.0f;
        reinterpret_cast<float4*>(orow)[q] = f;
    }
    for (int q = tot4 * 4 + tid; q < tilesz; q += TILE_TPB) {
        int k = s_tile[q];
        orow[q] = k ? s_bias[k & 7] : 0.0f;
    }
}

extern "C" void kernel_launch(void* const* d_in, const int* in_sizes, int n_in,
                              void* d_out, int out_size) {
    const float* b   = (const float*)d_in[1];
    const int*   src = (const int*)d_in[2];
    const int*   dst = (const int*)d_in[3];
    const int*   len = (const int*)d_in[4];
    float* out = (float*)d_out;

    long long total = (long long)out_size;
    int n = (int)llround(sqrt((double)total));
    int P = in_sizes[2];
    int maxpd = in_sizes[1];
    int nc = (n + (1 << CSH) - 1) >> CSH;
    int nbf = (n + 1) / 2;

    reset_kernel<<<(NBF_MAX + 255) / 256, 256>>>(nc, nbf);

    {
        int blocks = (P + CB_PER - 1) / CB_PER;
        size_t shmem = (size_t)CB_PER * sizeof(unsigned long long);  // 16KB
        coarse_bin_kernel<<<blocks, CB_TPB, shmem>>>(src, dst, len, P, maxpd, nc);
    }

    {
        size_t shmem = (size_t)FB_PER * sizeof(unsigned long long);  // 16KB
        fine_bin_kernel<<<nc * BPB_F, FB_TPB, shmem>>>();
    }

    {
        size_t shmem = (size_t)2 * n * sizeof(int);   // 48000B <= 48KB default
        tile_kernel<<<nbf, TILE_TPB, shmem>>>(out, b, n, maxpd);
    }
}

// round 9
// speedup vs baseline: 1.4255x; 1.4255x over previous
#include <cuda_runtime.h>
#include <cuda_bf16.h>
#include <math.h>

// Entry layout (52 bits used): [s:13][d:13][key:26]
//   key = ((i+1)<<3)|clamped  -> max(key) == last-write-wins (JAX scatter order)
#define KEY_MASK 0x3FFFFFFull
#define D_SHIFT 26
#define S_SHIFT 39

#define CSH 7                          // 128 rows per coarse bucket
#define NC_MAX 48
#define CAP_C 196608
#define NFPC 64                        // fine buckets per coarse (128 rows / 2)
#define NBF_MAX (NC_MAX * NFPC)        // 3072
#define CAP_F 4096

#define CB_TPB 256
#define CB_VPT 8
#define CB_PER (CB_TPB * CB_VPT)       // 2048 pairs / coarse-bin CTA
#define FB_TPB 256
#define FB_VPT 8
#define FB_PER (FB_TPB * FB_VPT)       // 2048 entries / fine-bin CTA
#define BPB_F (CAP_C / FB_PER)         // 96 fine-bin CTAs per coarse bucket
#define TILE_TPB 512
#define TILE_VPT 8                     // CAP_F / TILE_TPB

__device__ __align__(16) unsigned long long g_cbins[(size_t)NC_MAX * CAP_C];
__device__ __align__(16) unsigned long long g_fbins[(size_t)NBF_MAX * CAP_F];
__device__ int g_ccur[NC_MAX];
__device__ int g_fcur[NBF_MAX];

__global__ void reset_kernel(int nc, int nbf) {
    int i = blockIdx.x * blockDim.x + threadIdx.x;
    if (i < nc) g_ccur[i] = 0;
    if (i < nbf) g_fcur[i] = 0;
}

// ---------- Pass 1: pairs -> 48 coarse buckets (identical to R7) ----------
__global__ void coarse_bin_kernel(const int* __restrict__ src,
                                  const int* __restrict__ dst,
                                  const int* __restrict__ len,
                                  int P, int maxpd, int nc) {
    __shared__ int s_cnt[NC_MAX];
    __shared__ int s_start[NC_MAX];
    __shared__ int s_goff[NC_MAX];
    extern __shared__ unsigned long long s_buf[];   // CB_PER * 8 = 16KB

    int tid = threadIdx.x;
    int base = blockIdx.x * CB_PER;
    if (tid < nc) s_cnt[tid] = 0;
    __syncthreads();

    unsigned long long e[CB_VPT];
    int bk[CB_VPT];
#pragma unroll
    for (int j = 0; j < CB_VPT; j++) {
        int i = base + j * CB_TPB + tid;
        bk[j] = -1;
        if (i < P) {
            int s = src[i], d = dst[i], l = len[i];
            unsigned key = ((unsigned)(i + 1) << 3) | (unsigned)(min(l, maxpd) - 1);
            e[j] = ((unsigned long long)s << S_SHIFT)
                 | ((unsigned long long)d << D_SHIFT)
                 | (unsigned long long)key;
            bk[j] = s >> CSH;
            atomicAdd(&s_cnt[bk[j]], 1);
        }
    }
    __syncthreads();
    if (tid == 0) {
        int acc = 0;
        for (int b = 0; b < nc; b++) { s_start[b] = acc; acc += s_cnt[b]; }
    }
    __syncthreads();
    if (tid < nc) {
        int c = s_cnt[tid];
        int gb = (c > 0) ? atomicAdd(&g_ccur[tid], c) : 0;
        s_goff[tid] = gb - s_start[tid];
    }
    __syncthreads();
#pragma unroll
    for (int j = 0; j < CB_VPT; j++) {
        if (bk[j] >= 0) {
            int p = atomicAdd(&s_start[bk[j]], 1);
            s_buf[p] = e[j];
        }
    }
    __syncthreads();
    int tot = min(CB_PER, P - base);
    for (int k = tid; k < tot; k += CB_TPB) {
        unsigned long long ee = s_buf[k];
        int b = (int)(ee >> (S_SHIFT + CSH));
        int gpos = s_goff[b] + k;
        if ((unsigned)gpos < (unsigned)CAP_C)
            g_cbins[(size_t)b * CAP_C + gpos] = ee;
    }
}

// ---------- Pass 2: coarse -> fine buckets (identical to R7) ----------
__global__ void fine_bin_kernel() {
    __shared__ int s_cnt[NFPC];
    __shared__ int s_start[NFPC];
    __shared__ int s_goff[NFPC];
    extern __shared__ unsigned long long s_buf[];   // FB_PER * 8 = 16KB

    int c = blockIdx.x / BPB_F;
    int blk = blockIdx.x % BPB_F;
    int count = min(g_ccur[c], (int)CAP_C);
    int base = blk * FB_PER;
    if (base >= count) return;
    int tot = min(FB_PER, count - base);
    const unsigned long long* cb = g_cbins + (size_t)c * CAP_C + base;

    int tid = threadIdx.x;
    if (tid < NFPC) s_cnt[tid] = 0;
    __syncthreads();

    unsigned long long e[FB_VPT];
    int bk[FB_VPT];
#pragma unroll
    for (int j = 0; j < FB_VPT; j++) {
        int k = j * FB_TPB + tid;
        bk[j] = -1;
        if (k < tot) {
            e[j] = cb[k];
            int s = (int)(e[j] >> S_SHIFT);
            bk[j] = (s >> 1) & (NFPC - 1);
            atomicAdd(&s_cnt[bk[j]], 1);
        }
    }
    __syncthreads();
    if (tid == 0) {
        int acc = 0;
        for (int b = 0; b < NFPC; b++) { s_start[b] = acc; acc += s_cnt[b]; }
    }
    __syncthreads();
    if (tid < NFPC) {
        int cnt = s_cnt[tid];
        int gb = (cnt > 0) ? atomicAdd(&g_fcur[c * NFPC + tid], cnt) : 0;
        s_goff[tid] = gb - s_start[tid];
    }
    __syncthreads();
#pragma unroll
    for (int j = 0; j < FB_VPT; j++) {
        if (bk[j] >= 0) {
            int p = atomicAdd(&s_start[bk[j]], 1);
            s_buf[p] = e[j];
        }
    }
    __syncthreads();
    for (int k = tid; k < tot; k += FB_TPB) {
        unsigned long long ee = s_buf[k];
        int s = (int)(ee >> S_SHIFT);
        int fb = s >> 1;
        int gpos = s_goff[fb & (NFPC - 1)] + k;
        if ((unsigned)gpos < (unsigned)CAP_F)
            g_fbins[(size_t)fb * CAP_F + gpos] = ee;
    }
}

// ---------- Pass 3: fine bucket -> 2-row smem tile -> single output write ----
__global__ void tile_kernel(float* __restrict__ out, const float* __restrict__ bvals,
                            int n, int maxpd) {
    extern __shared__ int s_tile[];    // 2 * n ints = 48000B for n=6000
    __shared__ float s_bias[8];
    int tid = threadIdx.x;
    int bucket = blockIdx.x;
    int row0 = bucket * 2;
    int rows = min(2, n - row0);
    int tilesz = rows * n;

    if (tid < 8) s_bias[tid] = (tid < maxpd) ? bvals[tid] : 0.0f;
    {
        int4 z4 = make_int4(0, 0, 0, 0);
        int t4 = tilesz >> 2;
        for (int i = tid; i < t4; i += TILE_TPB)
            reinterpret_cast<int4*>(s_tile)[i] = z4;
        for (int i = (t4 << 2) + tid; i < tilesz; i += TILE_TPB) s_tile[i] = 0;
    }
    __syncthreads();

    int cnt = min(g_fcur[bucket], (int)CAP_F);
    const unsigned long long* bin = g_fbins + (size_t)bucket * CAP_F;

    // cache entries in registers with COMPILE-TIME indexed arrays
    // (fixed stride k = j*TILE_TPB + tid; j literal after unroll -> no spills)
    int slot[TILE_VPT];
    int key[TILE_VPT];
#pragma unroll
    for (int j = 0; j < TILE_VPT; j++) {
        int k = j * TILE_TPB + tid;
        slot[j] = -1;
        if (k < cnt) {
            unsigned long long v = bin[k];
            int s = (int)(v >> S_SHIFT);
            int d = (int)(v >> D_SHIFT) & 0x1FFF;
            slot[j] = (s - row0) * n + d;
            key[j] = (int)(v & KEY_MASK);
        }
    }
    // phase 1: plain racing writes (some writer wins)
#pragma unroll
    for (int j = 0; j < TILE_VPT; j++)
        if (slot[j] >= 0) s_tile[slot[j]] = key[j];
    __syncthreads();
    // phase 2: repair — only true collisions pay an atomic
#pragma unroll
    for (int j = 0; j < TILE_VPT; j++)
        if (slot[j] >= 0 && s_tile[slot[j]] < key[j])
            atomicMax(&s_tile[slot[j]], key[j]);
    __syncthreads();

    float* orow = out + (size_t)row0 * n;
    int tot4 = tilesz >> 2;
    for (int q = tid; q < tot4; q += TILE_TPB) {
        int4 k4 = reinterpret_cast<const int4*>(s_tile)[q];
        float4 f;
        f.x = k4.x ? s_bias[k4.x & 7] : 0.0f;
        f.y = k4.y ? s_bias[k4.y & 7] : 0.0f;
        f.z = k4.z ? s_bias[k4.z & 7] : 0.0f;
        f.w = k4.w ? s_bias[k4.w & 7] : 0.0f;
        reinterpret_cast<float4*>(orow)[q] = f;
    }
    for (int q = tot4 * 4 + tid; q < tilesz; q += TILE_TPB) {
        int k = s_tile[q];
        orow[q] = k ? s_bias[k & 7] : 0.0f;
    }
}

extern "C" void kernel_launch(void* const* d_in, const int* in_sizes, int n_in,
                              void* d_out, int out_size) {
    const float* b   = (const float*)d_in[1];
    const int*   src = (const int*)d_in[2];
    const int*   dst = (const int*)d_in[3];
    const int*   len = (const int*)d_in[4];
    float* out = (float*)d_out;

    long long total = (long long)out_size;
    int n = (int)llround(sqrt((double)total));
    int P = in_sizes[2];
    int maxpd = in_sizes[1];
    int nc = (n + (1 << CSH) - 1) >> CSH;
    int nbf = (n + 1) / 2;

    reset_kernel<<<(NBF_MAX + 255) / 256, 256>>>(nc, nbf);

    {
        int blocks = (P + CB_PER - 1) / CB_PER;
        size_t shmem = (size_t)CB_PER * sizeof(unsigned long long);  // 16KB
        coarse_bin_kernel<<<blocks, CB_TPB, shmem>>>(src, dst, len, P, maxpd, nc);
    }

    {
        size_t shmem = (size_t)FB_PER * sizeof(unsigned long long);  // 16KB
        fine_bin_kernel<<<nc * BPB_F, FB_TPB, shmem>>>();
    }

    {
        size_t shmem = (size_t)2 * n * sizeof(int);   // 48000B <= 48KB default
        tile_kernel<<<nbf, TILE_TPB, shmem>>>(out, b, n, maxpd);
    }
}